// round 11
// baseline (speedup 1.0000x reference)
#include <cuda_runtime.h>
#include <math.h>

#define Nn   20000
#define Bb   128
#define Ee   320000
#define FIN  768
#define RAWF 5000
#define Hh   256
#define Cc   4
#define CH   100   // nodes per pooling chunk

// ---------------- scratch (static device globals; no allocation) ----------------
__device__ int      g_indeg1[Nn], g_indeg2[Nn];
__device__ int      g_off1[Nn + 1], g_off2[Nn + 1];
__device__ int      g_cur1[Nn], g_cur2[Nn];
__device__ int      g_src1[Ee], g_src2[Ee];
__device__ float    g_dinv1[Nn], g_dinv2[Nn];
__device__ int      g_cnt[Bb];
__device__ float    g_Hbuf[(size_t)Nn * Hh];
__device__ float    g_Xbuf[(size_t)Nn * Hh];
__device__ float    g_msum[Bb * RAWF];          // raw-feature segment sums
__device__ float    g_a2[(size_t)Bb * 2 * RAWF]; // [mean | root] rows for branch-2 MLP
__device__ float    g_nx1[Bb * 512];
__device__ float    g_nx2[Bb * Hh];
__device__ float    g_acc0[Bb * Hh], g_acc1[Bb * Hh], g_acc2[Bb * Hh]; // mean-pool sums
__device__ unsigned g_maxacc[Bb * Hh];          // max-pool (uint floats >= 0)
__device__ float    g_cat5[Bb * 5 * Hh];

// ---------------- setup kernels ----------------
__global__ void k_zero() {
    int i = blockIdx.x * blockDim.x + threadIdx.x;
    if (i < Nn) { g_indeg1[i] = 0; g_indeg2[i] = 0; g_cur1[i] = 0; g_cur2[i] = 0; }
    if (i < Bb) g_cnt[i] = 0;
    if (i < Bb * RAWF) g_msum[i] = 0.f;
    if (i < Bb * Hh) { g_acc0[i] = 0.f; g_acc1[i] = 0.f; g_acc2[i] = 0.f; g_maxacc[i] = 0u; }
}

__global__ void k_deg(const int* __restrict__ ei, const int* __restrict__ rei) {
    int e = blockIdx.x * blockDim.x + threadIdx.x;
    if (e < Ee) {
        atomicAdd(&g_indeg1[ei[Ee + e]], 1);
        atomicAdd(&g_indeg2[rei[Ee + e]], 1);
    }
}

__global__ void k_dinv() {
    int i = blockIdx.x * blockDim.x + threadIdx.x;
    if (i < Nn) {
        g_dinv1[i] = rsqrtf((float)g_indeg1[i] + 1.0f);
        g_dinv2[i] = rsqrtf((float)g_indeg2[i] + 1.0f);
    }
}

__global__ void k_cnt_hist(const int* __restrict__ batch) {
    int i = blockIdx.x * blockDim.x + threadIdx.x;
    if (i < Nn) atomicAdd(&g_cnt[batch[i]], 1);
}

__global__ void k_scan1() {
    __shared__ int ssum[1024];
    int t = threadIdx.x;
    const int n = Nn;
    int per = (n + 1023) / 1024;
    int s = 0;
    for (int i = 0; i < per; i++) { int idx = t * per + i; if (idx < n) s += g_indeg1[idx]; }
    ssum[t] = s; __syncthreads();
    for (int d = 1; d < 1024; d <<= 1) {
        int v = (t >= d) ? ssum[t - d] : 0; __syncthreads();
        ssum[t] += v; __syncthreads();
    }
    int base = (t == 0) ? 0 : ssum[t - 1];
    for (int i = 0; i < per; i++) { int idx = t * per + i; if (idx < n) { g_off1[idx] = base; base += g_indeg1[idx]; } }
    if (t == 1023) g_off1[n] = ssum[1023];
}
__global__ void k_scan2() {
    __shared__ int ssum[1024];
    int t = threadIdx.x;
    const int n = Nn;
    int per = (n + 1023) / 1024;
    int s = 0;
    for (int i = 0; i < per; i++) { int idx = t * per + i; if (idx < n) s += g_indeg2[idx]; }
    ssum[t] = s; __syncthreads();
    for (int d = 1; d < 1024; d <<= 1) {
        int v = (t >= d) ? ssum[t - d] : 0; __syncthreads();
        ssum[t] += v; __syncthreads();
    }
    int base = (t == 0) ? 0 : ssum[t - 1];
    for (int i = 0; i < per; i++) { int idx = t * per + i; if (idx < n) { g_off2[idx] = base; base += g_indeg2[idx]; } }
    if (t == 1023) g_off2[n] = ssum[1023];
}

__global__ void k_fill1(const int* __restrict__ ei) {
    int e = blockIdx.x * blockDim.x + threadIdx.x;
    if (e < Ee) {
        int s = ei[e], d = ei[Ee + e];
        int p = g_off1[d] + atomicAdd(&g_cur1[d], 1);
        g_src1[p] = s;
    }
}
__global__ void k_fill2(const int* __restrict__ rei) {
    int e = blockIdx.x * blockDim.x + threadIdx.x;
    if (e < Ee) {
        int s = rei[e], d = rei[Ee + e];
        int p = g_off2[d] + atomicAdd(&g_cur2[d], 1);
        g_src2[p] = s;
    }
}

// ---------------- big SGEMM body: C = A[M,Kd] @ B[Kd,Nd], Nd=256 ----------------
__device__ __forceinline__ void sgemm_body(const float* __restrict__ A,
                                           const float* __restrict__ Bm,
                                           float* __restrict__ Cm, int M, int Kd, int Nd) {
    __shared__ float As[8][128];
    __shared__ float Bs[8][128];
    int tid = threadIdx.x;
    int m0 = blockIdx.x * 128, n0 = blockIdx.y * 128;
    int tx = tid & 15, ty = tid >> 4;
    float acc[8][8];
#pragma unroll
    for (int i = 0; i < 8; i++)
#pragma unroll
        for (int j = 0; j < 8; j++) acc[i][j] = 0.f;
    int ar = tid >> 1, ak = (tid & 1) * 4;
    int bk = tid >> 5, bn = (tid & 31) * 4;
    for (int k0 = 0; k0 < Kd; k0 += 8) {
        float4 av;
        int row = m0 + ar;
        if (row < M) av = *(const float4*)(A + (size_t)row * Kd + k0 + ak);
        else av = make_float4(0.f, 0.f, 0.f, 0.f);
        As[ak + 0][ar] = av.x; As[ak + 1][ar] = av.y;
        As[ak + 2][ar] = av.z; As[ak + 3][ar] = av.w;
        float4 bv = *(const float4*)(Bm + (size_t)(k0 + bk) * Nd + n0 + bn);
        *(float4*)&Bs[bk][bn] = bv;
        __syncthreads();
#pragma unroll
        for (int kk = 0; kk < 8; kk++) {
            float a[8], b[8];
            *(float4*)&a[0] = *(float4*)&As[kk][ty * 8];
            *(float4*)&a[4] = *(float4*)&As[kk][ty * 8 + 4];
            *(float4*)&b[0] = *(float4*)&Bs[kk][tx * 8];
            *(float4*)&b[4] = *(float4*)&Bs[kk][tx * 8 + 4];
#pragma unroll
            for (int i = 0; i < 8; i++)
#pragma unroll
                for (int j = 0; j < 8; j++) acc[i][j] += a[i] * b[j];
        }
        __syncthreads();
    }
#pragma unroll
    for (int i = 0; i < 8; i++) {
        int row = m0 + ty * 8 + i;
        if (row < M) {
            float* cp = Cm + (size_t)row * Nd + n0 + tx * 8;
            *(float4*)cp       = make_float4(acc[i][0], acc[i][1], acc[i][2], acc[i][3]);
            *(float4*)(cp + 4) = make_float4(acc[i][4], acc[i][5], acc[i][6], acc[i][7]);
        }
    }
}
__global__ void sgemm_g1(const float* __restrict__ A, const float* __restrict__ W) {
    sgemm_body(A, W, g_Hbuf, Nn, FIN, Hh);
}
__global__ void sgemm_dx(const float* __restrict__ A, const float* __restrict__ W) {
    sgemm_body(A, W, g_Hbuf, Nn, RAWF, Hh);
}
__global__ void sgemm_x(const float* __restrict__ W) {
    sgemm_body(g_Xbuf, W, g_Hbuf, Nn, Hh, Hh);
}

// ---------------- GCN propagate (CSR gather) + bias + relu ----------------
__global__ void gather1(const float* __restrict__ bias) {
    int i = blockIdx.x, f = threadIdx.x;
    float di = g_dinv1[i];
    float acc = di * di * g_Hbuf[(size_t)i * Hh + f];
    int e0 = g_off1[i], e1 = g_off1[i + 1];
    for (int e = e0; e < e1; e++) {
        int s = g_src1[e];
        acc += di * g_dinv1[s] * g_Hbuf[(size_t)s * Hh + f];
    }
    acc += bias[f];
    g_Xbuf[(size_t)i * Hh + f] = fmaxf(acc, 0.f);
}
__global__ void gather2(const float* __restrict__ bias) {
    int i = blockIdx.x, f = threadIdx.x;
    float di = g_dinv2[i];
    float acc = di * di * g_Hbuf[(size_t)i * Hh + f];
    int e0 = g_off2[i], e1 = g_off2[i + 1];
    for (int e = e0; e < e1; e++) {
        int s = g_src2[e];
        acc += di * g_dinv2[s] * g_Hbuf[(size_t)s * Hh + f];
    }
    acc += bias[f];
    g_Xbuf[(size_t)i * Hh + f] = fmaxf(acc, 0.f);
}

// ---------------- pooling: batch-driven atomic segment reductions ----------------
__global__ void pacc_mean(int which, const int* __restrict__ batch) {
    float* dst = (which == 0) ? g_acc0 : (which == 1) ? g_acc1 : g_acc2;
    int f = threadIdx.x;
    int i0 = blockIdx.x * CH;
    int i1 = min(i0 + CH, Nn);
    if (i0 >= Nn) return;
    int cur = batch[i0];
    float acc = 0.f;
    for (int i = i0; i < i1; i++) {
        int b = batch[i];
        if (b != cur) { atomicAdd(&dst[cur * Hh + f], acc); acc = 0.f; cur = b; }
        acc += g_Xbuf[(size_t)i * Hh + f];
    }
    atomicAdd(&dst[cur * Hh + f], acc);
}

__global__ void pacc_max(const int* __restrict__ batch) {
    int f = threadIdx.x;
    int i0 = blockIdx.x * CH;
    int i1 = min(i0 + CH, Nn);
    if (i0 >= Nn) return;
    int cur = batch[i0];
    float m = 0.f;
    for (int i = i0; i < i1; i++) {
        int b = batch[i];
        if (b != cur) { atomicMax(&g_maxacc[cur * Hh + f], __float_as_uint(m)); m = 0.f; cur = b; }
        m = fmaxf(m, g_Xbuf[(size_t)i * Hh + f]);
    }
    atomicMax(&g_maxacc[cur * Hh + f], __float_as_uint(m));
}

// Raw-feature segment sums (5000 features) into g_msum.
__global__ void k_msum(const float* __restrict__ dx, const int* __restrict__ batch) {
    int f = blockIdx.y * 256 + threadIdx.x;
    if (f >= RAWF) return;
    int i0 = blockIdx.x * CH;
    int i1 = min(i0 + CH, Nn);
    if (i0 >= Nn) return;
    int cur = batch[i0];
    float acc = 0.f;
    for (int i = i0; i < i1; i++) {
        int b = batch[i];
        if (b != cur) { atomicAdd(&g_msum[cur * RAWF + f], acc); acc = 0.f; cur = b; }
        acc += dx[(size_t)i * RAWF + f];
    }
    atomicAdd(&g_msum[cur * RAWF + f], acc);
}

// ---------------- branch-2 MLP ----------------
// Build A2 rows = [mean(data_x per graph) | data_x[root]]
__global__ void k_a2(const float* __restrict__ dx, const int* __restrict__ root) {
    int r = blockIdx.x;
    int c = blockIdx.y * 256 + threadIdx.x;
    if (c >= 2 * RAWF) return;
    float v;
    if (c < RAWF) v = g_msum[r * RAWF + c] / fmaxf((float)g_cnt[r], 1.f);
    else          v = dx[(size_t)root[r] * RAWF + (c - RAWF)];
    g_a2[(size_t)r * (2 * RAWF) + c] = v;
}

// Layer 1: 4 graphs per block, 512 threads (= all output cols), k unrolled by 4.
// nx1[g][c] = prelu( A2[g] . Wl1[:,c] + bl1[c] )
__global__ void k_mlp1(const float* __restrict__ Wl1, const float* __restrict__ bl1,
                       const float* __restrict__ pa) {
    int g0 = blockIdx.x * 4;
    int c = threadIdx.x;
    const float* a0 = &g_a2[(size_t)(g0 + 0) * (2 * RAWF)];
    const float* a1 = &g_a2[(size_t)(g0 + 1) * (2 * RAWF)];
    const float* a2 = &g_a2[(size_t)(g0 + 2) * (2 * RAWF)];
    const float* a3 = &g_a2[(size_t)(g0 + 3) * (2 * RAWF)];
    float s0 = 0.f, s1 = 0.f, s2 = 0.f, s3 = 0.f;
    for (int k = 0; k < 2 * RAWF; k += 4) {
        float4 v0 = *(const float4*)(a0 + k);
        float4 v1 = *(const float4*)(a1 + k);
        float4 v2 = *(const float4*)(a2 + k);
        float4 v3 = *(const float4*)(a3 + k);
        float w0 = Wl1[(size_t)(k + 0) * 512 + c];
        float w1 = Wl1[(size_t)(k + 1) * 512 + c];
        float w2 = Wl1[(size_t)(k + 2) * 512 + c];
        float w3 = Wl1[(size_t)(k + 3) * 512 + c];
        s0 += v0.x * w0 + v0.y * w1 + v0.z * w2 + v0.w * w3;
        s1 += v1.x * w0 + v1.y * w1 + v1.z * w2 + v1.w * w3;
        s2 += v2.x * w0 + v2.y * w1 + v2.z * w2 + v2.w * w3;
        s3 += v3.x * w0 + v3.y * w1 + v3.z * w2 + v3.w * w3;
    }
    float bb = bl1[c];
    float a = *pa;
    s0 += bb; s1 += bb; s2 += bb; s3 += bb;
    g_nx1[(g0 + 0) * 512 + c] = (s0 >= 0.f) ? s0 : a * s0;
    g_nx1[(g0 + 1) * 512 + c] = (s1 >= 0.f) ? s1 : a * s1;
    g_nx1[(g0 + 2) * 512 + c] = (s2 >= 0.f) ? s2 : a * s2;
    g_nx1[(g0 + 3) * 512 + c] = (s3 >= 0.f) ? s3 : a * s3;
}

// Layer 2: nx2[r][c] = prelu( nx1[r] . Wl2[:,c] + bl2[c] )
__global__ void k_mlp2(const float* __restrict__ Wl2, const float* __restrict__ bl2,
                       const float* __restrict__ pa) {
    int r = blockIdx.x;
    int c = threadIdx.x;
    float acc = 0.f;
    for (int k = 0; k < 512; k++)
        acc += g_nx1[r * 512 + k] * Wl2[(size_t)k * Hh + c];
    acc += bl2[c];
    float a = *pa;
    g_nx2[r * Hh + c] = (acc >= 0.f) ? acc : a * acc;
}

// ---------------- concat (divisions folded in) + classifier + log_softmax ----------
__global__ void k_cat5() {
    int g = blockIdx.x, f = threadIdx.x;
    float inv = 1.f / fmaxf((float)g_cnt[g], 1.f);
    float* o = &g_cat5[g * (5 * Hh)];
    o[f]          = g_acc0[g * Hh + f] * inv;
    o[Hh + f]     = g_acc1[g * Hh + f] * inv;
    o[2 * Hh + f] = g_acc2[g * Hh + f] * inv;
    o[3 * Hh + f] = g_nx2[g * Hh + f];
    o[4 * Hh + f] = __uint_as_float(g_maxacc[g * Hh + f]);
}

__global__ void k_final(const float* __restrict__ W5, const float* __restrict__ b5,
                        float* __restrict__ out) {
    __shared__ float sh[128];
    int r = blockIdx.x, t = threadIdx.x;
    int c = t & 3, kk = t >> 2;
    float acc = 0.f;
    for (int k = kk; k < 5 * Hh; k += 32)
        acc += g_cat5[r * (5 * Hh) + k] * W5[k * Cc + c];
    sh[t] = acc;
    __syncthreads();
    if (t < 4) {
        float s = 0.f;
        for (int q = 0; q < 32; q++) s += sh[q * 4 + t];
        s += b5[t];
        sh[t] = s;
    }
    __syncthreads();
    if (t == 0) {
        float m = sh[0];
        for (int q = 1; q < 4; q++) m = fmaxf(m, sh[q]);
        float lse = 0.f;
        for (int q = 0; q < 4; q++) lse += expf(sh[q] - m);
        lse = logf(lse);
        for (int q = 0; q < 4; q++) out[r * Cc + q] = sh[q] - m - lse;
    }
}

// ---------------- launch ----------------
extern "C" void kernel_launch(void* const* d_in, const int* in_sizes, int n_in,
                              void* d_out, int out_size) {
    const float* graph_x = (const float*)d_in[0];
    const float* data_x  = (const float*)d_in[2];
    const int*   ei      = (const int*)d_in[3];
    const int*   rei     = (const int*)d_in[4];
    const int*   batch   = (const int*)d_in[6];   // x_batch (== graph_batch)
    const int*   root    = (const int*)d_in[7];
    const float* W1  = (const float*)d_in[8];
    const float* b1  = (const float*)d_in[9];
    const float* Wc0 = (const float*)d_in[10];
    const float* bc0 = (const float*)d_in[11];
    const float* Wc1 = (const float*)d_in[12];
    const float* bc1 = (const float*)d_in[13];
    const float* Wc2 = (const float*)d_in[14];
    const float* bc2 = (const float*)d_in[15];
    const float* Wl1 = (const float*)d_in[16];
    const float* bl1 = (const float*)d_in[17];
    const float* Wl2 = (const float*)d_in[18];
    const float* bl2 = (const float*)d_in[19];
    const float* pa  = (const float*)d_in[20];
    const float* W5  = (const float*)d_in[21];
    const float* b5  = (const float*)d_in[22];
    float* out = (float*)d_out;

    // --- preprocessing ---
    k_zero<<<(Bb * RAWF + 255) / 256, 256>>>();
    k_deg<<<(Ee + 255) / 256, 256>>>(ei, rei);
    k_dinv<<<(Nn + 255) / 256, 256>>>();
    k_scan1<<<1, 1024>>>();
    k_scan2<<<1, 1024>>>();
    k_fill1<<<(Ee + 255) / 256, 256>>>(ei);
    k_fill2<<<(Ee + 255) / 256, 256>>>(rei);
    k_cnt_hist<<<(Nn + 255) / 256, 256>>>(batch);

    dim3 gemmGrid((Nn + 127) / 128, Hh / 128);
    int poolBlocks = (Nn + CH - 1) / CH;

    // --- branch 1: GCN(graph_x) -> relu -> max pool ---
    sgemm_g1<<<gemmGrid, 256>>>(graph_x, W1);
    gather1<<<Nn, 256>>>(b1);
    pacc_max<<<poolBlocks, 256>>>(batch);

    // --- branch 2: segment mean + root + 2-layer PReLU MLP ---
    k_msum<<<dim3(poolBlocks, (RAWF + 255) / 256), 256>>>(data_x, batch);
    k_a2<<<dim3(Bb, (2 * RAWF + 255) / 256), 256>>>(data_x, root);
    k_mlp1<<<Bb / 4, 512>>>(Wl1, bl1, pa);
    k_mlp2<<<Bb, 256>>>(Wl2, bl2, pa);

    // --- branch 3: 3x GCN over raw graph (CSR gather), mean pool each layer ---
    sgemm_dx<<<gemmGrid, 256>>>(data_x, Wc0);
    gather2<<<Nn, 256>>>(bc0);
    pacc_mean<<<poolBlocks, 256>>>(0, batch);

    sgemm_x<<<gemmGrid, 256>>>(Wc1);
    gather2<<<Nn, 256>>>(bc1);
    pacc_mean<<<poolBlocks, 256>>>(1, batch);

    sgemm_x<<<gemmGrid, 256>>>(Wc2);
    gather2<<<Nn, 256>>>(bc2);
    pacc_mean<<<poolBlocks, 256>>>(2, batch);

    // --- final ---
    k_cat5<<<Bb, 256>>>();
    k_final<<<Bb, 128>>>(W5, b5, out);
}

// round 12
// speedup vs baseline: 1.0877x; 1.0877x over previous
#include <cuda_runtime.h>
#include <cuda_bf16.h>
#include <mma.h>
#include <math.h>

using namespace nvcuda;

#define Nn   20000
#define NPAD 20096   // Nn rounded up to 128 so wmma epilogue stores stay in-bounds
#define Bb   128
#define Ee   320000
#define FIN  768
#define RAWF 5000
#define Hh   256
#define Cc   4
#define CH   100   // nodes per pooling chunk

// ---------------- scratch (static device globals; no allocation) ----------------
__device__ int      g_indeg1[Nn], g_indeg2[Nn];
__device__ int      g_off1[Nn + 1];
__device__ int      g_cur1[Nn];
__device__ int      g_src1[Ee];
__device__ float    g_dinv1[Nn], g_dinv2[Nn];
__device__ int      g_cnt[Bb];
__device__ float    g_Hbuf[(size_t)NPAD * Hh];
__device__ float    g_Xbuf[(size_t)NPAD * Hh];
__device__ float    g_Pbuf[(size_t)Nn * Hh];     // scatter accumulation buffer
__device__ float    g_msum[Bb * RAWF];           // raw-feature segment sums
__device__ float    g_a2[(size_t)Bb * 2 * RAWF]; // [mean | root] rows for branch-2 MLP
__device__ float    g_nx1[Bb * 512];
__device__ float    g_nx2[Bb * Hh];
__device__ float    g_acc0[Bb * Hh], g_acc1[Bb * Hh], g_acc2[Bb * Hh]; // mean-pool sums
__device__ unsigned g_maxacc[Bb * Hh];           // max-pool (uint floats >= 0)
__device__ float    g_cat5[Bb * 5 * Hh];

// ---------------- setup kernels ----------------
__global__ void k_zero() {
    int i = blockIdx.x * blockDim.x + threadIdx.x;
    if (i < Nn) { g_indeg1[i] = 0; g_indeg2[i] = 0; g_cur1[i] = 0; }
    if (i < Bb) g_cnt[i] = 0;
    if (i < Bb * RAWF) g_msum[i] = 0.f;
    if (i < Bb * Hh) { g_acc0[i] = 0.f; g_acc1[i] = 0.f; g_acc2[i] = 0.f; g_maxacc[i] = 0u; }
}

__global__ void k_zeroP() {
    size_t i = (size_t)blockIdx.x * blockDim.x + threadIdx.x;
    if (i < (size_t)Nn * Hh) g_Pbuf[i] = 0.f;
}

__global__ void k_deg(const int* __restrict__ ei, const int* __restrict__ rei) {
    int e = blockIdx.x * blockDim.x + threadIdx.x;
    if (e < Ee) {
        atomicAdd(&g_indeg1[ei[Ee + e]], 1);
        atomicAdd(&g_indeg2[rei[Ee + e]], 1);
    }
}

__global__ void k_dinv() {
    int i = blockIdx.x * blockDim.x + threadIdx.x;
    if (i < Nn) {
        g_dinv1[i] = rsqrtf((float)g_indeg1[i] + 1.0f);
        g_dinv2[i] = rsqrtf((float)g_indeg2[i] + 1.0f);
    }
}

__global__ void k_cnt_hist(const int* __restrict__ batch) {
    int i = blockIdx.x * blockDim.x + threadIdx.x;
    if (i < Nn) atomicAdd(&g_cnt[batch[i]], 1);
}

__global__ void k_scan1() {
    __shared__ int ssum[1024];
    int t = threadIdx.x;
    const int n = Nn;
    int per = (n + 1023) / 1024;
    int s = 0;
    for (int i = 0; i < per; i++) { int idx = t * per + i; if (idx < n) s += g_indeg1[idx]; }
    ssum[t] = s; __syncthreads();
    for (int d = 1; d < 1024; d <<= 1) {
        int v = (t >= d) ? ssum[t - d] : 0; __syncthreads();
        ssum[t] += v; __syncthreads();
    }
    int base = (t == 0) ? 0 : ssum[t - 1];
    for (int i = 0; i < per; i++) { int idx = t * per + i; if (idx < n) { g_off1[idx] = base; base += g_indeg1[idx]; } }
    if (t == 1023) g_off1[n] = ssum[1023];
}

__global__ void k_fill1(const int* __restrict__ ei) {
    int e = blockIdx.x * blockDim.x + threadIdx.x;
    if (e < Ee) {
        int s = ei[e], d = ei[Ee + e];
        int p = g_off1[d] + atomicAdd(&g_cur1[d], 1);
        g_src1[p] = s;
    }
}

// ---------------- bf16-split tensor-core GEMM ----------------
// C[M,N] = A[M,K] @ W[K,N], fp32 in/out, computed as Ah*Wh + Ah*Wl + Al*Wh
// with Ah=bf16(A), Al=bf16(A-Ah). BM=128, BN=128, BK=32, 256 threads (8 warps).
// C rows may be written up to round_up(M,128): caller provides padded C.
#define BKK 32
__global__ __launch_bounds__(256, 2)
void wgemm(const float* __restrict__ A, const float* __restrict__ W,
           float* __restrict__ C, int M, int K, int N) {
    __shared__ __nv_bfloat16 sAh[128][BKK];
    __shared__ __nv_bfloat16 sAl[128][BKK];
    __shared__ __nv_bfloat16 sWh[BKK][136];
    __shared__ __nv_bfloat16 sWl[BKK][136];

    int tid = threadIdx.x;
    int wid = tid >> 5;
    int m0 = blockIdx.x * 128, n0 = blockIdx.y * 128;
    int wr = (wid >> 1) * 32;   // warp row offset: 0/32/64/96
    int wc = (wid & 1) * 64;    // warp col offset: 0/64

    wmma::fragment<wmma::accumulator, 16, 16, 16, float> acc[2][4];
#pragma unroll
    for (int i = 0; i < 2; i++)
#pragma unroll
        for (int j = 0; j < 4; j++) wmma::fill_fragment(acc[i][j], 0.f);

    for (int k0 = 0; k0 < K; k0 += BKK) {
        // stage A tile [128 x 32] with hi/lo split
#pragma unroll
        for (int i = tid; i < 128 * BKK; i += 256) {
            int r = i >> 5, c = i & 31;
            float v = 0.f;
            if (m0 + r < M && k0 + c < K) v = A[(size_t)(m0 + r) * K + k0 + c];
            __nv_bfloat16 h = __float2bfloat16(v);
            sAh[r][c] = h;
            sAl[r][c] = __float2bfloat16(v - __bfloat162float(h));
        }
        // stage W tile [32 x 128] with hi/lo split
#pragma unroll
        for (int i = tid; i < BKK * 128; i += 256) {
            int r = i >> 7, c = i & 127;
            float v = 0.f;
            if (k0 + r < K) v = W[(size_t)(k0 + r) * N + n0 + c];
            __nv_bfloat16 h = __float2bfloat16(v);
            sWh[r][c] = h;
            sWl[r][c] = __float2bfloat16(v - __bfloat162float(h));
        }
        __syncthreads();

#pragma unroll
        for (int kk = 0; kk < BKK; kk += 16) {
            wmma::fragment<wmma::matrix_b, 16, 16, 16, __nv_bfloat16, wmma::row_major> fbh[4], fbl[4];
#pragma unroll
            for (int j = 0; j < 4; j++) {
                wmma::load_matrix_sync(fbh[j], &sWh[kk][wc + 16 * j], 136);
                wmma::load_matrix_sync(fbl[j], &sWl[kk][wc + 16 * j], 136);
            }
#pragma unroll
            for (int ti = 0; ti < 2; ti++) {
                wmma::fragment<wmma::matrix_a, 16, 16, 16, __nv_bfloat16, wmma::row_major> fah, fal;
                wmma::load_matrix_sync(fah, &sAh[wr + 16 * ti][kk], BKK);
                wmma::load_matrix_sync(fal, &sAl[wr + 16 * ti][kk], BKK);
#pragma unroll
                for (int j = 0; j < 4; j++) {
                    wmma::mma_sync(acc[ti][j], fah, fbh[j], acc[ti][j]);
                    wmma::mma_sync(acc[ti][j], fah, fbl[j], acc[ti][j]);
                    wmma::mma_sync(acc[ti][j], fal, fbh[j], acc[ti][j]);
                }
            }
        }
        __syncthreads();
    }

#pragma unroll
    for (int ti = 0; ti < 2; ti++)
#pragma unroll
        for (int j = 0; j < 4; j++)
            wmma::store_matrix_sync(C + (size_t)(m0 + wr + 16 * ti) * N + n0 + wc + 16 * j,
                                    acc[ti][j], N, wmma::mem_row_major);
}

// ---------------- branch-1 GCN propagate (CSR gather) + bias + relu ----------------
__global__ void gather1(const float* __restrict__ bias) {
    int i = blockIdx.x, f = threadIdx.x;
    float di = g_dinv1[i];
    float acc = di * di * g_Hbuf[(size_t)i * Hh + f];
    int e0 = g_off1[i], e1 = g_off1[i + 1];
    for (int e = e0; e < e1; e++) {
        int s = g_src1[e];
        acc += di * g_dinv1[s] * g_Hbuf[(size_t)s * Hh + f];
    }
    acc += bias[f];
    g_Xbuf[(size_t)i * Hh + f] = fmaxf(acc, 0.f);
}

// ---------------- branch-3 GCN propagate: edge-parallel atomic scatter ----------
__global__ void k_scatter(const int* __restrict__ rei) {
    int e = blockIdx.x;
    int s = rei[e], d = rei[Ee + e];
    float w = g_dinv2[s] * g_dinv2[d];
    int f = threadIdx.x;
    atomicAdd(&g_Pbuf[(size_t)d * Hh + f], w * g_Hbuf[(size_t)s * Hh + f]);
}

__global__ void k_selfrelu(const float* __restrict__ bias) {
    int i = blockIdx.x, f = threadIdx.x;
    float di = g_dinv2[i];
    float acc = g_Pbuf[(size_t)i * Hh + f] + di * di * g_Hbuf[(size_t)i * Hh + f] + bias[f];
    g_Xbuf[(size_t)i * Hh + f] = fmaxf(acc, 0.f);
}

// ---------------- pooling: batch-driven atomic segment reductions ----------------
__global__ void pacc_mean(int which, const int* __restrict__ batch) {
    float* dst = (which == 0) ? g_acc0 : (which == 1) ? g_acc1 : g_acc2;
    int f = threadIdx.x;
    int i0 = blockIdx.x * CH;
    int i1 = min(i0 + CH, Nn);
    if (i0 >= Nn) return;
    int cur = batch[i0];
    float acc = 0.f;
    for (int i = i0; i < i1; i++) {
        int b = batch[i];
        if (b != cur) { atomicAdd(&dst[cur * Hh + f], acc); acc = 0.f; cur = b; }
        acc += g_Xbuf[(size_t)i * Hh + f];
    }
    atomicAdd(&dst[cur * Hh + f], acc);
}

__global__ void pacc_max(const int* __restrict__ batch) {
    int f = threadIdx.x;
    int i0 = blockIdx.x * CH;
    int i1 = min(i0 + CH, Nn);
    if (i0 >= Nn) return;
    int cur = batch[i0];
    float m = 0.f;
    for (int i = i0; i < i1; i++) {
        int b = batch[i];
        if (b != cur) { atomicMax(&g_maxacc[cur * Hh + f], __float_as_uint(m)); m = 0.f; cur = b; }
        m = fmaxf(m, g_Xbuf[(size_t)i * Hh + f]);
    }
    atomicMax(&g_maxacc[cur * Hh + f], __float_as_uint(m));
}

// Raw-feature segment sums (5000 features) into g_msum.
__global__ void k_msum(const float* __restrict__ dx, const int* __restrict__ batch) {
    int f = blockIdx.y * 256 + threadIdx.x;
    if (f >= RAWF) return;
    int i0 = blockIdx.x * CH;
    int i1 = min(i0 + CH, Nn);
    if (i0 >= Nn) return;
    int cur = batch[i0];
    float acc = 0.f;
    for (int i = i0; i < i1; i++) {
        int b = batch[i];
        if (b != cur) { atomicAdd(&g_msum[cur * RAWF + f], acc); acc = 0.f; cur = b; }
        acc += dx[(size_t)i * RAWF + f];
    }
    atomicAdd(&g_msum[cur * RAWF + f], acc);
}

// ---------------- branch-2 MLP ----------------
__global__ void k_a2(const float* __restrict__ dx, const int* __restrict__ root) {
    int r = blockIdx.x;
    int c = blockIdx.y * 256 + threadIdx.x;
    if (c >= 2 * RAWF) return;
    float v;
    if (c < RAWF) v = g_msum[r * RAWF + c] / fmaxf((float)g_cnt[r], 1.f);
    else          v = dx[(size_t)root[r] * RAWF + (c - RAWF)];
    g_a2[(size_t)r * (2 * RAWF) + c] = v;
}

// Layer 1: 4 graphs per block, 512 threads (= all output cols), k unrolled by 4.
__global__ void k_mlp1(const float* __restrict__ Wl1, const float* __restrict__ bl1,
                       const float* __restrict__ pa) {
    int g0 = blockIdx.x * 4;
    int c = threadIdx.x;
    const float* a0 = &g_a2[(size_t)(g0 + 0) * (2 * RAWF)];
    const float* a1 = &g_a2[(size_t)(g0 + 1) * (2 * RAWF)];
    const float* a2 = &g_a2[(size_t)(g0 + 2) * (2 * RAWF)];
    const float* a3 = &g_a2[(size_t)(g0 + 3) * (2 * RAWF)];
    float s0 = 0.f, s1 = 0.f, s2 = 0.f, s3 = 0.f;
    for (int k = 0; k < 2 * RAWF; k += 4) {
        float4 v0 = *(const float4*)(a0 + k);
        float4 v1 = *(const float4*)(a1 + k);
        float4 v2 = *(const float4*)(a2 + k);
        float4 v3 = *(const float4*)(a3 + k);
        float w0 = Wl1[(size_t)(k + 0) * 512 + c];
        float w1 = Wl1[(size_t)(k + 1) * 512 + c];
        float w2 = Wl1[(size_t)(k + 2) * 512 + c];
        float w3 = Wl1[(size_t)(k + 3) * 512 + c];
        s0 += v0.x * w0 + v0.y * w1 + v0.z * w2 + v0.w * w3;
        s1 += v1.x * w0 + v1.y * w1 + v1.z * w2 + v1.w * w3;
        s2 += v2.x * w0 + v2.y * w1 + v2.z * w2 + v2.w * w3;
        s3 += v3.x * w0 + v3.y * w1 + v3.z * w2 + v3.w * w3;
    }
    float bb = bl1[c];
    float a = *pa;
    s0 += bb; s1 += bb; s2 += bb; s3 += bb;
    g_nx1[(g0 + 0) * 512 + c] = (s0 >= 0.f) ? s0 : a * s0;
    g_nx1[(g0 + 1) * 512 + c] = (s1 >= 0.f) ? s1 : a * s1;
    g_nx1[(g0 + 2) * 512 + c] = (s2 >= 0.f) ? s2 : a * s2;
    g_nx1[(g0 + 3) * 512 + c] = (s3 >= 0.f) ? s3 : a * s3;
}

__global__ void k_mlp2(const float* __restrict__ Wl2, const float* __restrict__ bl2,
                       const float* __restrict__ pa) {
    int r = blockIdx.x;
    int c = threadIdx.x;
    float acc = 0.f;
    for (int k = 0; k < 512; k++)
        acc += g_nx1[r * 512 + k] * Wl2[(size_t)k * Hh + c];
    acc += bl2[c];
    float a = *pa;
    g_nx2[r * Hh + c] = (acc >= 0.f) ? acc : a * acc;
}

// ---------------- concat (divisions folded in) + classifier + log_softmax ----------
__global__ void k_cat5() {
    int g = blockIdx.x, f = threadIdx.x;
    float inv = 1.f / fmaxf((float)g_cnt[g], 1.f);
    float* o = &g_cat5[g * (5 * Hh)];
    o[f]          = g_acc0[g * Hh + f] * inv;
    o[Hh + f]     = g_acc1[g * Hh + f] * inv;
    o[2 * Hh + f] = g_acc2[g * Hh + f] * inv;
    o[3 * Hh + f] = g_nx2[g * Hh + f];
    o[4 * Hh + f] = __uint_as_float(g_maxacc[g * Hh + f]);
}

__global__ void k_final(const float* __restrict__ W5, const float* __restrict__ b5,
                        float* __restrict__ out) {
    __shared__ float sh[128];
    int r = blockIdx.x, t = threadIdx.x;
    int c = t & 3, kk = t >> 2;
    float acc = 0.f;
    for (int k = kk; k < 5 * Hh; k += 32)
        acc += g_cat5[r * (5 * Hh) + k] * W5[k * Cc + c];
    sh[t] = acc;
    __syncthreads();
    if (t < 4) {
        float s = 0.f;
        for (int q = 0; q < 32; q++) s += sh[q * 4 + t];
        s += b5[t];
        sh[t] = s;
    }
    __syncthreads();
    if (t == 0) {
        float m = sh[0];
        for (int q = 1; q < 4; q++) m = fmaxf(m, sh[q]);
        float lse = 0.f;
        for (int q = 0; q < 4; q++) lse += expf(sh[q] - m);
        lse = logf(lse);
        for (int q = 0; q < 4; q++) out[r * Cc + q] = sh[q] - m - lse;
    }
}

// ---------------- launch ----------------
extern "C" void kernel_launch(void* const* d_in, const int* in_sizes, int n_in,
                              void* d_out, int out_size) {
    const float* graph_x = (const float*)d_in[0];
    const float* data_x  = (const float*)d_in[2];
    const int*   ei      = (const int*)d_in[3];
    const int*   rei     = (const int*)d_in[4];
    const int*   batch   = (const int*)d_in[6];   // x_batch (== graph_batch)
    const int*   root    = (const int*)d_in[7];
    const float* W1  = (const float*)d_in[8];
    const float* b1  = (const float*)d_in[9];
    const float* Wc0 = (const float*)d_in[10];
    const float* bc0 = (const float*)d_in[11];
    const float* Wc1 = (const float*)d_in[12];
    const float* bc1 = (const float*)d_in[13];
    const float* Wc2 = (const float*)d_in[14];
    const float* bc2 = (const float*)d_in[15];
    const float* Wl1 = (const float*)d_in[16];
    const float* bl1 = (const float*)d_in[17];
    const float* Wl2 = (const float*)d_in[18];
    const float* bl2 = (const float*)d_in[19];
    const float* pa  = (const float*)d_in[20];
    const float* W5  = (const float*)d_in[21];
    const float* b5  = (const float*)d_in[22];
    float* out = (float*)d_out;

    // device-global addresses usable from host via cudaGetSymbolAddress are not
    // allowed to allocate; instead we pass via kernels that reference symbols.
    // wgemm needs raw pointers to g_Hbuf/g_Xbuf: obtain device pointers once.
    static float* p_Hbuf = nullptr;
    static float* p_Xbuf = nullptr;
    if (!p_Hbuf) {
        cudaGetSymbolAddress((void**)&p_Hbuf, g_Hbuf);
        cudaGetSymbolAddress((void**)&p_Xbuf, g_Xbuf);
    }

    // --- preprocessing ---
    k_zero<<<(Bb * RAWF + 255) / 256, 256>>>();
    k_deg<<<(Ee + 255) / 256, 256>>>(ei, rei);
    k_dinv<<<(Nn + 255) / 256, 256>>>();
    k_scan1<<<1, 1024>>>();
    k_fill1<<<(Ee + 255) / 256, 256>>>(ei);
    k_cnt_hist<<<(Nn + 255) / 256, 256>>>(batch);

    dim3 gemmGrid((Nn + 127) / 128, Hh / 128);
    int poolBlocks = (Nn + CH - 1) / CH;
    int pbZero = (int)(((size_t)Nn * Hh + 255) / 256);

    // --- branch 1: GCN(graph_x) -> relu -> max pool ---
    wgemm<<<gemmGrid, 256>>>(graph_x, W1, p_Hbuf, Nn, FIN, Hh);
    gather1<<<Nn, 256>>>(b1);
    pacc_max<<<poolBlocks, 256>>>(batch);

    // --- branch 2: segment mean + root + 2-layer PReLU MLP ---
    k_msum<<<dim3(poolBlocks, (RAWF + 255) / 256), 256>>>(data_x, batch);
    k_a2<<<dim3(Bb, (2 * RAWF + 255) / 256), 256>>>(data_x, root);
    k_mlp1<<<Bb / 4, 512>>>(Wl1, bl1, pa);
    k_mlp2<<<Bb, 256>>>(Wl2, bl2, pa);

    // --- branch 3: 3x GCN over raw graph (scatter-atomic propagate), mean pools ---
    wgemm<<<gemmGrid, 256>>>(data_x, Wc0, p_Hbuf, Nn, RAWF, Hh);
    k_zeroP<<<pbZero, 256>>>();
    k_scatter<<<Ee, 256>>>(rei);
    k_selfrelu<<<Nn, 256>>>(bc0);
    pacc_mean<<<poolBlocks, 256>>>(0, batch);

    wgemm<<<gemmGrid, 256>>>(p_Xbuf, Wc1, p_Hbuf, Nn, Hh, Hh);
    k_zeroP<<<pbZero, 256>>>();
    k_scatter<<<Ee, 256>>>(rei);
    k_selfrelu<<<Nn, 256>>>(bc1);
    pacc_mean<<<poolBlocks, 256>>>(1, batch);

    wgemm<<<gemmGrid, 256>>>(p_Xbuf, Wc2, p_Hbuf, Nn, Hh, Hh);
    k_zeroP<<<pbZero, 256>>>();
    k_scatter<<<Ee, 256>>>(rei);
    k_selfrelu<<<Nn, 256>>>(bc2);
    pacc_mean<<<poolBlocks, 256>>>(2, batch);

    // --- final ---
    k_cat5<<<Bb, 256>>>();
    k_final<<<Bb, 128>>>(W5, b5, out);
}